// round 4
// baseline (speedup 1.0000x reference)
#include <cuda_runtime.h>

#define NT_MAX 200000
#define ETT_MAX 1100000

// ---------------------------------------------------------------------------
// Scratch (__device__ globals — allocation-free rule)
// ---------------------------------------------------------------------------
__device__ float g_agg  [NT_MAX * 5];
__device__ float g_fused[NT_MAX * 64];
__device__ float g_Bdep [NT_MAX * 64];
__device__ float g_Cdep [NT_MAX * 64];
__device__ float g_Brev [NT_MAX * 64];
__device__ float g_Crev [NT_MAX * 64];
__device__ float g_Sdep [NT_MAX * 64];
__device__ float g_Srev [NT_MAX * 64];
__device__ int   g_degD [NT_MAX];
__device__ int   g_degR [NT_MAX];
__device__ int   g_ptrD [NT_MAX + 1];
__device__ int   g_ptrR [NT_MAX + 1];
__device__ int   g_curD [NT_MAX];
__device__ int   g_curR [NT_MAX];
__device__ int   g_srcD [ETT_MAX];
__device__ int   g_srcR [ETT_MAX];
__device__ int   g_bsumD[512];
__device__ int   g_bsumR[512];
__device__ float g_colsum[64];

typedef unsigned long long u64;

__device__ __forceinline__ float leaky(float x) { return x > 0.f ? x : 0.01f * x; }

__device__ __forceinline__ float warp_sum(float v) {
#pragma unroll
    for (int o = 16; o > 0; o >>= 1) v += __shfl_xor_sync(0xffffffffu, v, o);
    return v;
}

// ---- packed f32x2 helpers (Blackwell FFMA2 path, PTX-only) ----------------
__device__ __forceinline__ u64 pack2(float x) {
    u64 d;
    asm("mov.b64 %0, {%1, %1};" : "=l"(d) : "r"(__float_as_uint(x)));
    return d;
}
__device__ __forceinline__ void fma2(u64& d, u64 a, u64 b) {
    asm("fma.rn.f32x2 %0, %1, %2, %0;" : "+l"(d) : "l"(a), "l"(b));
}
__device__ __forceinline__ u64 add2(u64 a, u64 b) {
    u64 d; asm("add.rn.f32x2 %0, %1, %2;" : "=l"(d) : "l"(a), "l"(b)); return d;
}
__device__ __forceinline__ u64 mul2(u64 a, u64 b) {
    u64 d; asm("mul.rn.f32x2 %0, %1, %2;" : "=l"(d) : "l"(a), "l"(b)); return d;
}
// leaky(x) = 0.505*x + 0.495*|x|   (exact identity, branch-free, per-lane)
#define C505_2 0x3F0147AE3F0147AEULL
#define C495_2 0x3EFD70A43EFD70A4ULL
#define ABSM_2 0x7FFFFFFF7FFFFFFFULL
__device__ __forceinline__ u64 leaky2(u64 v) {
    u64 r = mul2(v & ABSM_2, C495_2);
    fma2(r, v, C505_2);
    return r;
}

// ---------------------------------------------------------------------------
// K0: zero accumulators
// ---------------------------------------------------------------------------
__global__ void k_zero(int n) {
    int i = blockIdx.x * blockDim.x + threadIdx.x;
    if (i < n * 5) g_agg[i] = 0.f;
    if (i < n) { g_degD[i] = 0; g_degR[i] = 0; }
    if (i < 64) g_colsum[i] = 0.f;
}

// ---------------------------------------------------------------------------
// K1: data->task scatter-add
// ---------------------------------------------------------------------------
__global__ void k_dt(const float* __restrict__ data_x,
                     const int* __restrict__ src, const int* __restrict__ dst, int E) {
    int e = blockIdx.x * blockDim.x + threadIdx.x;
    if (e >= E) return;
    int s = __ldg(&src[e]);
    int d = __ldg(&dst[e]);
    const float* xr = data_x + s * 5;
    float* ar = g_agg + d * 5;
#pragma unroll
    for (int k = 0; k < 5; k++) atomicAdd(ar + k, __ldg(&xr[k]));
}

// ---------------------------------------------------------------------------
// K1b: degree histograms
// ---------------------------------------------------------------------------
__global__ void k_hist(const int* __restrict__ tsrc, const int* __restrict__ tdst, int E) {
    int e = blockIdx.x * blockDim.x + threadIdx.x;
    if (e >= E) return;
    atomicAdd(&g_degD[__ldg(&tdst[e])], 1);
    atomicAdd(&g_degR[__ldg(&tsrc[e])], 1);
}

// ---------------------------------------------------------------------------
// Scan stage 1
// ---------------------------------------------------------------------------
__global__ __launch_bounds__(256) void k_scan_blk(int n) {
    int arr = blockIdx.y;
    const int* deg = arr ? g_degR : g_degD;
    int* ptr = arr ? g_ptrR : g_ptrD;
    int* bsum = arr ? g_bsumR : g_bsumD;
    __shared__ int sh[256];
    int tid = threadIdx.x;
    int base = blockIdx.x * 1024;
    int v[4]; int s = 0;
#pragma unroll
    for (int j = 0; j < 4; j++) {
        int idx = base + tid * 4 + j;
        v[j] = (idx < n) ? deg[idx] : 0;
        s += v[j];
    }
    sh[tid] = s;
    __syncthreads();
#pragma unroll
    for (int d = 1; d < 256; d <<= 1) {
        int t = 0;
        if (tid >= d) t = sh[tid - d];
        __syncthreads();
        sh[tid] += t;
        __syncthreads();
    }
    int off = sh[tid] - s;
#pragma unroll
    for (int j = 0; j < 4; j++) {
        int idx = base + tid * 4 + j;
        if (idx < n) ptr[idx] = off;
        off += v[j];
    }
    if (tid == 0) bsum[blockIdx.x] = sh[255];
}

// ---------------------------------------------------------------------------
// Scan stage 2
// ---------------------------------------------------------------------------
__global__ void k_scan_top(int nblk) {
    int tid = threadIdx.x;
    if (tid == 0) {
        int a = 0;
        for (int i = 0; i < nblk; i++) { int t = g_bsumD[i]; g_bsumD[i] = a; a += t; }
    }
    if (tid == 1) {
        int a = 0;
        for (int i = 0; i < nblk; i++) { int t = g_bsumR[i]; g_bsumR[i] = a; a += t; }
    }
}

// ---------------------------------------------------------------------------
// Scan stage 3
// ---------------------------------------------------------------------------
__global__ __launch_bounds__(256) void k_scan_fix(int n, int E) {
    int arr = blockIdx.y;
    int* ptr = arr ? g_ptrR : g_ptrD;
    int* cur = arr ? g_curR : g_curD;
    const int* bsum = arr ? g_bsumR : g_bsumD;
    int off = bsum[blockIdx.x];
    int base = blockIdx.x * 1024 + threadIdx.x * 4;
#pragma unroll
    for (int j = 0; j < 4; j++) {
        int idx = base + j;
        if (idx < n) { int v = ptr[idx] + off; ptr[idx] = v; cur[idx] = v; }
    }
    if (blockIdx.x == 0 && threadIdx.x == 0) ptr[n] = E;
}

// ---------------------------------------------------------------------------
// K1c: scatter edges into CSR
// ---------------------------------------------------------------------------
__global__ void k_scatter(const int* __restrict__ tsrc, const int* __restrict__ tdst, int E) {
    int e = blockIdx.x * blockDim.x + threadIdx.x;
    if (e >= E) return;
    int s = __ldg(&tsrc[e]);
    int d = __ldg(&tdst[e]);
    int p = atomicAdd(&g_curD[d], 1);
    g_srcD[p] = s;
    int q = atomicAdd(&g_curR[s], 1);
    g_srcR[q] = d;
}

// ---------------------------------------------------------------------------
// K2: fused = leaky(LN(agg @ Wrel + brel + tasks @ Wroot))   (warp per row)
// ---------------------------------------------------------------------------
__global__ void k_fused(const float* __restrict__ tasks_x,
                        const float* __restrict__ Wrel, const float* __restrict__ brel,
                        const float* __restrict__ Wroot,
                        const float* __restrict__ lng, const float* __restrict__ lnb,
                        int n) {
    int gt = blockIdx.x * blockDim.x + threadIdx.x;
    int r = gt >> 5, lane = gt & 31;
    if (r >= n) return;
    float p0 = __ldg(&brel[lane]);
    float p1 = __ldg(&brel[lane + 32]);
    const float* ar = g_agg + r * 5;
#pragma unroll
    for (int k = 0; k < 5; k++) {
        float a = ar[k];
        p0 += a * __ldg(&Wrel[k * 64 + lane]);
        p1 += a * __ldg(&Wrel[k * 64 + lane + 32]);
    }
    const float* tr = tasks_x + r * 12;
#pragma unroll
    for (int k = 0; k < 12; k++) {
        float t = __ldg(&tr[k]);
        p0 += t * __ldg(&Wroot[k * 64 + lane]);
        p1 += t * __ldg(&Wroot[k * 64 + lane + 32]);
    }
    float m = warp_sum(p0 + p1) * (1.f / 64.f);
    float d0 = p0 - m, d1 = p1 - m;
    float v = warp_sum(d0 * d0 + d1 * d1) * (1.f / 64.f);
    float inv = rsqrtf(v + 1e-5f);
    float y0 = leaky(d0 * inv * __ldg(&lng[lane])      + __ldg(&lnb[lane]));
    float y1 = leaky(d1 * inv * __ldg(&lng[lane + 32]) + __ldg(&lnb[lane + 32]));
    g_fused[r * 64 + lane]      = y0;
    g_fused[r * 64 + lane + 32] = y1;
}

// ---------------------------------------------------------------------------
// K3: B = fused @ W1b, C = fused @ (W1a - W1b) for one conv (FFMA2 path)
// ---------------------------------------------------------------------------
__global__ __launch_bounds__(256) void k_gemm_bc(const float* __restrict__ W1,
                                                 int n, int conv) {
    extern __shared__ float sm[];
    float* Ws = sm;            // [64][128]
    float* Xs = sm + 8192;     // [128][65]
    int tid = threadIdx.x;
    int row0 = blockIdx.x * 128;

    for (int idx = tid; idx < 8192; idx += 256) {
        int k = idx >> 7, j = idx & 127;
        float wB = W1[(64 + k) * 64 + (j & 63)];
        Ws[idx] = (j < 64) ? wB : (W1[k * 64 + (j - 64)] - wB);
    }
#pragma unroll
    for (int it = 0; it < 8; it++) {
        int fi = tid + it * 256;
        int r = fi >> 4, c4 = (fi & 15) * 4;
        float4 v = make_float4(0.f, 0.f, 0.f, 0.f);
        int row = row0 + r;
        if (row < n) v = *reinterpret_cast<const float4*>(&g_fused[row * 64 + c4]);
        Xs[r * 65 + c4 + 0] = v.x;
        Xs[r * 65 + c4 + 1] = v.y;
        Xs[r * 65 + c4 + 2] = v.z;
        Xs[r * 65 + c4 + 3] = v.w;
    }
    __syncthreads();

    int tr = tid >> 4, tc = tid & 15;
    u64 acc[8][4];
#pragma unroll
    for (int i = 0; i < 8; i++)
#pragma unroll
        for (int j = 0; j < 4; j++) acc[i][j] = 0ULL;

#pragma unroll 4
    for (int k = 0; k < 64; k++) {
        ulonglong2 wa = *reinterpret_cast<ulonglong2*>(&Ws[k * 128 + tc * 8]);
        ulonglong2 wb = *reinterpret_cast<ulonglong2*>(&Ws[k * 128 + tc * 8 + 4]);
#pragma unroll
        for (int i = 0; i < 8; i++) {
            u64 xx = pack2(Xs[(tr * 8 + i) * 65 + k]);
            fma2(acc[i][0], xx, wa.x);
            fma2(acc[i][1], xx, wa.y);
            fma2(acc[i][2], xx, wb.x);
            fma2(acc[i][3], xx, wb.y);
        }
    }

    float* Bo = conv ? g_Brev : g_Bdep;
    float* Co = conv ? g_Crev : g_Cdep;
    float* O = (tc < 8) ? Bo : Co;
    int cbase = (tc < 8) ? tc * 8 : (tc - 8) * 8;
#pragma unroll
    for (int i = 0; i < 8; i++) {
        int row = row0 + tr * 8 + i;
        if (row < n) {
            *reinterpret_cast<ulonglong2*>(&O[row * 64 + cbase]) =
                make_ulonglong2(acc[i][0], acc[i][1]);
            *reinterpret_cast<ulonglong2*>(&O[row * 64 + cbase + 4]) =
                make_ulonglong2(acc[i][2], acc[i][3]);
        }
    }
}

// ---------------------------------------------------------------------------
// K4: edge aggregation. Warp per node, lane owns packed channels (2l, 2l+1).
//   S[r] = sum_{src in CSR[r]} leaky(C[r] + B[src] + b1)   (f32x2 throughout)
// ---------------------------------------------------------------------------
__global__ __launch_bounds__(256) void k_agg(const float* __restrict__ b1,
                                             int n, int conv) {
    const int* ptr  = conv ? g_ptrR : g_ptrD;
    const int* srcA = conv ? g_srcR : g_srcD;
    const float* B  = conv ? g_Brev : g_Bdep;
    const float* C  = conv ? g_Crev : g_Cdep;
    float* S        = conv ? g_Srev : g_Sdep;
    const unsigned FULL = 0xffffffffu;
    int lane = threadIdx.x & 31, wid = threadIdx.x >> 5;
    int r = blockIdx.x * 8 + wid;
    if (r >= n) return;
    int a0 = ptr[r], a1 = ptr[r + 1];
    u64 c2 = add2(*reinterpret_cast<const u64*>(&C[r * 64 + 2 * lane]),
                  *reinterpret_cast<const u64*>(&b1[2 * lane]));
    u64 s2 = 0ULL;
    for (int i0 = a0; i0 < a1; i0 += 32) {
        int cnt = min(32, a1 - i0);
        int mi = (lane < cnt) ? srcA[i0 + lane] : 0;
        int j = 0;
        for (; j + 4 <= cnt; j += 4) {
            int x0 = __shfl_sync(FULL, mi, j);
            int x1 = __shfl_sync(FULL, mi, j + 1);
            int x2 = __shfl_sync(FULL, mi, j + 2);
            int x3 = __shfl_sync(FULL, mi, j + 3);
            u64 b0 = *reinterpret_cast<const u64*>(&B[x0 * 64 + 2 * lane]);
            u64 b1v = *reinterpret_cast<const u64*>(&B[x1 * 64 + 2 * lane]);
            u64 b2v = *reinterpret_cast<const u64*>(&B[x2 * 64 + 2 * lane]);
            u64 b3v = *reinterpret_cast<const u64*>(&B[x3 * 64 + 2 * lane]);
            s2 = add2(s2, leaky2(add2(c2, b0)));
            s2 = add2(s2, leaky2(add2(c2, b1v)));
            s2 = add2(s2, leaky2(add2(c2, b2v)));
            s2 = add2(s2, leaky2(add2(c2, b3v)));
        }
        for (; j < cnt; j++) {
            int xs = __shfl_sync(FULL, mi, j);
            u64 b = *reinterpret_cast<const u64*>(&B[xs * 64 + 2 * lane]);
            s2 = add2(s2, leaky2(add2(c2, b)));
        }
    }
    *reinterpret_cast<u64*>(&S[r * 64 + 2 * lane]) = s2;
}

// ---------------------------------------------------------------------------
// K5: tiled tail (FFMA2). Block = 128 rows. Thread: 4 rows (tr=tid>>3),
// 8 cols (tc=tid&7).
// smem floats: W 8192 | Xs 8704 | Dp 8704 | Rv 8704 | V 448 | CP 2048 | DG 256
// ---------------------------------------------------------------------------
#define TS 68

__global__ __launch_bounds__(256) void k_tail2(
    const float* __restrict__ depW2, const float* __restrict__ depb2,
    const float* __restrict__ depg,  const float* __restrict__ depb,
    const float* __restrict__ revW2, const float* __restrict__ revb2,
    const float* __restrict__ revg,  const float* __restrict__ revb,
    const float* __restrict__ projW, const float* __restrict__ projb,
    float* __restrict__ out, int n) {
    extern __shared__ float sm[];
    float* W  = sm;            // 8192
    float* Xs = sm + 8192;     // 8704
    float* Dp = sm + 16896;    // 8704
    float* Rv = sm + 25600;    // 8704
    float* V  = sm + 34304;    // 448
    float* CP = sm + 34752;    // 2048
    float* DG = sm + 36800;    // 256

    int tid = threadIdx.x;
    int row0 = blockIdx.x * 128;
    int tr = tid >> 3, tc = tid & 7;      // 32 row-groups x 4 rows; 8 col-groups x 8 cols
    int lane = tid & 31, wid = tid >> 5;

    if (tid < 64) {
        V[tid]       = depb2[tid];
        V[64 + tid]  = revb2[tid];
        V[128 + tid] = depg[tid];
        V[192 + tid] = depb[tid];
        V[256 + tid] = revg[tid];
        V[320 + tid] = revb[tid];
        V[384 + tid] = projb[tid];
    }
    if (tid < 128) {
        int row = row0 + tid;
        DG[tid]       = (row < n) ? (float)(g_ptrD[row + 1] - g_ptrD[row]) : 0.f;
        DG[128 + tid] = (row < n) ? (float)(g_ptrR[row + 1] - g_ptrR[row]) : 0.f;
    }

    // ============ stage 1: dep ============
    for (int i = tid; i < 4096; i += 256) W[i] = depW2[i];
#pragma unroll
    for (int it = 0; it < 8; it++) {
        int fi = tid + it * 256;
        int r = fi >> 4, c4 = (fi & 15) * 4;
        float4 v = make_float4(0.f, 0.f, 0.f, 0.f);
        int row = row0 + r;
        if (row < n) v = *reinterpret_cast<const float4*>(&g_Sdep[row * 64 + c4]);
        *reinterpret_cast<float4*>(&Xs[r * TS + c4]) = v;
    }
    __syncthreads();

    {
        u64 acc[4][4];
#pragma unroll
        for (int i = 0; i < 4; i++)
#pragma unroll
            for (int j = 0; j < 4; j++) acc[i][j] = 0ULL;
#pragma unroll 4
        for (int k = 0; k < 64; k++) {
            ulonglong2 wa = *reinterpret_cast<ulonglong2*>(&W[k * 64 + tc * 8]);
            ulonglong2 wb = *reinterpret_cast<ulonglong2*>(&W[k * 64 + tc * 8 + 4]);
#pragma unroll
            for (int i = 0; i < 4; i++) {
                u64 xx = pack2(Xs[(tr * 4 + i) * TS + k]);
                fma2(acc[i][0], xx, wa.x);
                fma2(acc[i][1], xx, wa.y);
                fma2(acc[i][2], xx, wb.x);
                fma2(acc[i][3], xx, wb.y);
            }
        }
        ulonglong2 ba = *reinterpret_cast<ulonglong2*>(&V[tc * 8]);
        ulonglong2 bb = *reinterpret_cast<ulonglong2*>(&V[tc * 8 + 4]);
#pragma unroll
        for (int i = 0; i < 4; i++) {
            u64 dg = pack2(DG[tr * 4 + i]);
            fma2(acc[i][0], dg, ba.x);
            fma2(acc[i][1], dg, ba.y);
            fma2(acc[i][2], dg, bb.x);
            fma2(acc[i][3], dg, bb.y);
            *reinterpret_cast<ulonglong2*>(&Dp[(tr * 4 + i) * TS + tc * 8]) =
                make_ulonglong2(acc[i][0], acc[i][1]);
            *reinterpret_cast<ulonglong2*>(&Dp[(tr * 4 + i) * TS + tc * 8 + 4]) =
                make_ulonglong2(acc[i][2], acc[i][3]);
        }
    }
    __syncthreads();

    // LN dep (warp per row, 16 rows/warp); concurrently load W2r + S_rev
#pragma unroll
    for (int t = 0; t < 16; t++) {
        int row = wid * 16 + t;
        float h0 = Dp[row * TS + lane];
        float h1 = Dp[row * TS + 32 + lane];
        float m = warp_sum(h0 + h1) * (1.f / 64.f);
        float e0 = h0 - m, e1 = h1 - m;
        float v = warp_sum(e0 * e0 + e1 * e1) * (1.f / 64.f);
        float inv = rsqrtf(v + 1e-5f);
        Dp[row * TS + lane]      = leaky(e0 * inv * V[128 + lane] + V[192 + lane]);
        Dp[row * TS + 32 + lane] = leaky(e1 * inv * V[160 + lane] + V[224 + lane]);
    }
    for (int i = tid; i < 4096; i += 256) W[i] = revW2[i];
#pragma unroll
    for (int it = 0; it < 8; it++) {
        int fi = tid + it * 256;
        int r = fi >> 4, c4 = (fi & 15) * 4;
        float4 v = make_float4(0.f, 0.f, 0.f, 0.f);
        int row = row0 + r;
        if (row < n) v = *reinterpret_cast<const float4*>(&g_Srev[row * 64 + c4]);
        *reinterpret_cast<float4*>(&Xs[r * TS + c4]) = v;
    }
    __syncthreads();

    // ============ stage 2: rev ============
    {
        u64 acc[4][4];
#pragma unroll
        for (int i = 0; i < 4; i++)
#pragma unroll
            for (int j = 0; j < 4; j++) acc[i][j] = 0ULL;
#pragma unroll 4
        for (int k = 0; k < 64; k++) {
            ulonglong2 wa = *reinterpret_cast<ulonglong2*>(&W[k * 64 + tc * 8]);
            ulonglong2 wb = *reinterpret_cast<ulonglong2*>(&W[k * 64 + tc * 8 + 4]);
#pragma unroll
            for (int i = 0; i < 4; i++) {
                u64 xx = pack2(Xs[(tr * 4 + i) * TS + k]);
                fma2(acc[i][0], xx, wa.x);
                fma2(acc[i][1], xx, wa.y);
                fma2(acc[i][2], xx, wb.x);
                fma2(acc[i][3], xx, wb.y);
            }
        }
        ulonglong2 ba = *reinterpret_cast<ulonglong2*>(&V[64 + tc * 8]);
        ulonglong2 bb = *reinterpret_cast<ulonglong2*>(&V[64 + tc * 8 + 4]);
#pragma unroll
        for (int i = 0; i < 4; i++) {
            u64 dg = pack2(DG[128 + tr * 4 + i]);
            fma2(acc[i][0], dg, ba.x);
            fma2(acc[i][1], dg, ba.y);
            fma2(acc[i][2], dg, bb.x);
            fma2(acc[i][3], dg, bb.y);
            *reinterpret_cast<ulonglong2*>(&Rv[(tr * 4 + i) * TS + tc * 8]) =
                make_ulonglong2(acc[i][0], acc[i][1]);
            *reinterpret_cast<ulonglong2*>(&Rv[(tr * 4 + i) * TS + tc * 8 + 4]) =
                make_ulonglong2(acc[i][2], acc[i][3]);
        }
    }
    __syncthreads();

    // LN rev; concurrently load P
#pragma unroll
    for (int t = 0; t < 16; t++) {
        int row = wid * 16 + t;
        float h0 = Rv[row * TS + lane];
        float h1 = Rv[row * TS + 32 + lane];
        float m = warp_sum(h0 + h1) * (1.f / 64.f);
        float e0 = h0 - m, e1 = h1 - m;
        float v = warp_sum(e0 * e0 + e1 * e1) * (1.f / 64.f);
        float inv = rsqrtf(v + 1e-5f);
        Rv[row * TS + lane]      = leaky(e0 * inv * V[256 + lane] + V[320 + lane]);
        Rv[row * TS + 32 + lane] = leaky(e1 * inv * V[288 + lane] + V[352 + lane]);
    }
    for (int i = tid; i < 8192; i += 256) W[i] = projW[i];
    __syncthreads();

    // ============ stage 3: proj + reduce ============
    {
        u64 acc[4][4];
#pragma unroll
        for (int i = 0; i < 4; i++)
#pragma unroll
            for (int j = 0; j < 4; j++) acc[i][j] = 0ULL;
#pragma unroll 4
        for (int k = 0; k < 64; k++) {
            ulonglong2 wa = *reinterpret_cast<ulonglong2*>(&W[k * 64 + tc * 8]);
            ulonglong2 wb = *reinterpret_cast<ulonglong2*>(&W[k * 64 + tc * 8 + 4]);
#pragma unroll
            for (int i = 0; i < 4; i++) {
                u64 xx = pack2(Dp[(tr * 4 + i) * TS + k]);
                fma2(acc[i][0], xx, wa.x);
                fma2(acc[i][1], xx, wa.y);
                fma2(acc[i][2], xx, wb.x);
                fma2(acc[i][3], xx, wb.y);
            }
        }
#pragma unroll 4
        for (int k = 0; k < 64; k++) {
            ulonglong2 wa = *reinterpret_cast<ulonglong2*>(&W[(k + 64) * 64 + tc * 8]);
            ulonglong2 wb = *reinterpret_cast<ulonglong2*>(&W[(k + 64) * 64 + tc * 8 + 4]);
#pragma unroll
            for (int i = 0; i < 4; i++) {
                u64 xx = pack2(Rv[(tr * 4 + i) * TS + k]);
                fma2(acc[i][0], xx, wa.x);
                fma2(acc[i][1], xx, wa.y);
                fma2(acc[i][2], xx, wb.x);
                fma2(acc[i][3], xx, wb.y);
            }
        }
        ulonglong2 pa = *reinterpret_cast<ulonglong2*>(&V[384 + tc * 8]);
        ulonglong2 pb = *reinterpret_cast<ulonglong2*>(&V[384 + tc * 8 + 4]);
        u64 cs0 = 0ULL, cs1 = 0ULL, cs2 = 0ULL, cs3 = 0ULL;
#pragma unroll
        for (int i = 0; i < 4; i++) {
            int row = row0 + tr * 4 + i;
            u64 t0 = leaky2(add2(acc[i][0], pa.x));
            u64 t1 = leaky2(add2(acc[i][1], pa.y));
            u64 t2 = leaky2(add2(acc[i][2], pb.x));
            u64 t3 = leaky2(add2(acc[i][3], pb.y));
            if (row < n) {
                cs0 = add2(cs0, t0); cs1 = add2(cs1, t1);
                cs2 = add2(cs2, t2); cs3 = add2(cs3, t3);
            }
            if (row == 0) {
                *reinterpret_cast<ulonglong2*>(&out[64 + tc * 8])     = make_ulonglong2(t0, t1);
                *reinterpret_cast<ulonglong2*>(&out[64 + tc * 8 + 4]) = make_ulonglong2(t2, t3);
            }
        }
        *reinterpret_cast<ulonglong2*>(&CP[tr * 64 + tc * 8])     = make_ulonglong2(cs0, cs1);
        *reinterpret_cast<ulonglong2*>(&CP[tr * 64 + tc * 8 + 4]) = make_ulonglong2(cs2, cs3);
    }
    __syncthreads();
    if (tid < 64) {
        float s = 0.f;
#pragma unroll
        for (int g = 0; g < 32; g++) s += CP[g * 64 + tid];
        atomicAdd(&g_colsum[tid], s);
    }
}

// ---------------------------------------------------------------------------
// K6: finalize global state + device branch
// ---------------------------------------------------------------------------
__global__ void k_final(const int* __restrict__ counts,
                        const float* __restrict__ devx,
                        const float* __restrict__ timex,
                        const float* __restrict__ devW,
                        const float* __restrict__ devb,
                        float* __restrict__ out) {
    int tid = threadIdx.x;
    if (tid < 64) {
        int c = counts[0];
        if (c < 1) c = 1;
        out[tid] = g_colsum[tid] / (float)c;
    } else if (tid < 128) {
        int j = tid - 64;
        float p = devb[j];
#pragma unroll 8
        for (int k = 0; k < 96; k++) p += devx[k] * devW[k * 64 + j];
        p += (timex[0] * 1e-5f) * devW[96 * 64 + j];
        out[128 + j] = leaky(p);
    }
}

// ---------------------------------------------------------------------------
// Launch
// ---------------------------------------------------------------------------
extern "C" void kernel_launch(void* const* d_in, const int* in_sizes, int n_in,
                              void* d_out, int out_size) {
    const float* data_x    = (const float*)d_in[0];
    const float* tasks_x   = (const float*)d_in[1];
    const float* devices_x = (const float*)d_in[2];
    const float* time_x    = (const float*)d_in[3];
    const int*   dt_src    = (const int*)d_in[4];
    const int*   dt_dst    = (const int*)d_in[5];
    const int*   tt_src    = (const int*)d_in[6];
    const int*   tt_dst    = (const int*)d_in[7];
    const int*   counts    = (const int*)d_in[8];
    const float* gcWrel    = (const float*)d_in[9];
    const float* gcbrel    = (const float*)d_in[10];
    const float* gcWroot   = (const float*)d_in[11];
    const float* gclng     = (const float*)d_in[12];
    const float* gclnb     = (const float*)d_in[13];
    const float* depW1     = (const float*)d_in[14];
    const float* depb1     = (const float*)d_in[15];
    const float* depW2     = (const float*)d_in[16];
    const float* depb2     = (const float*)d_in[17];
    const float* deplng    = (const float*)d_in[18];
    const float* deplnb    = (const float*)d_in[19];
    const float* revW1     = (const float*)d_in[20];
    const float* revb1     = (const float*)d_in[21];
    const float* revW2     = (const float*)d_in[22];
    const float* revb2     = (const float*)d_in[23];
    const float* revlng    = (const float*)d_in[24];
    const float* revlnb    = (const float*)d_in[25];
    const float* devW      = (const float*)d_in[26];
    const float* devb      = (const float*)d_in[27];
    const float* projW     = (const float*)d_in[28];
    const float* projb     = (const float*)d_in[29];
    float* out = (float*)d_out;

    int n    = in_sizes[1] / 12;
    int e_dt = in_sizes[4];
    int e_tt = in_sizes[6];
    int nblk = (n + 1023) / 1024;

    cudaFuncSetAttribute(k_gemm_bc, cudaFuncAttributeMaxDynamicSharedMemorySize, 66048);
    cudaFuncSetAttribute(k_tail2,   cudaFuncAttributeMaxDynamicSharedMemorySize, 148224);

    k_zero<<<(n * 5 + 255) / 256, 256>>>(n);
    k_dt<<<(e_dt + 255) / 256, 256>>>(data_x, dt_src, dt_dst, e_dt);
    k_hist<<<(e_tt + 255) / 256, 256>>>(tt_src, tt_dst, e_tt);

    dim3 sg(nblk, 2);
    k_scan_blk<<<sg, 256>>>(n);
    k_scan_top<<<1, 32>>>(nblk);
    k_scan_fix<<<sg, 256>>>(n, e_tt);
    k_scatter<<<(e_tt + 255) / 256, 256>>>(tt_src, tt_dst, e_tt);

    k_fused<<<(n * 32 + 255) / 256, 256>>>(tasks_x, gcWrel, gcbrel, gcWroot, gclng, gclnb, n);

    int gb = (n + 127) / 128;
    k_gemm_bc<<<gb, 256, 66048>>>(depW1, n, 0);
    k_gemm_bc<<<gb, 256, 66048>>>(revW1, n, 1);

    int ab = (n + 7) / 8;
    k_agg<<<ab, 256>>>(depb1, n, 0);
    k_agg<<<ab, 256>>>(revb1, n, 1);

    k_tail2<<<gb, 256, 148224>>>(depW2, depb2, deplng, deplnb,
                                 revW2, revb2, revlng, revlnb,
                                 projW, projb, out, n);
    k_final<<<1, 128>>>(counts, devices_x, time_x, devW, devb, out);
}